// round 7
// baseline (speedup 1.0000x reference)
#include <cuda_runtime.h>
#include <cuda_fp16.h>
#include <cstdint>

#define Hd     1536
#define FOURH  6144
#define NS     1008      // (T-1)*B = 63*16 sequential steps
#define CHUNKS 6         // 1536 / 256
#define SC     3         // chunks cached in smem per warp

// ---------------- static device scratch ----------------
__device__ float  g_xpre[(size_t)NS * FOURH];                   // layer-0 input projection
__device__ __align__(16) __half g_Wh[3][(size_t)FOURH * Hd];    // fp16 weights, natural k-order
__device__ float  g_h0[2][Hd];
__device__ float  g_h1[2][Hd];
__device__ float  g_pa[2][FOURH];
__device__ unsigned int g_bar_count = 0;
__device__ unsigned int g_bar_gen   = 0;

// dyn smem: [ sh0h: 1536 half | sh1h: 1536 half | wcache: 32 warps * SC*4*256 halves ]
#define WC_PER_WARP (SC * 4 * 256)                 // halves (6 KB per warp)
#define SMEM_BYTES  (2 * Hd * 2 + 32 * WC_PER_WARP * 2)

// ---------------- software grid barrier (cg-style: syncthreads + t0 fence) -----------
__device__ __forceinline__ void grid_barrier(int G) {
    __syncthreads();
    if (threadIdx.x == 0) {
        __threadfence();
        volatile unsigned int* genp = &g_bar_gen;
        unsigned int gen = *genp;
        unsigned int a = atomicAdd(&g_bar_count, 1u);
        if (a == (unsigned int)(G - 1)) {
            atomicExch(&g_bar_count, 0u);
            __threadfence();
            *genp = gen + 1u;
        } else {
            while (*genp == gen) { }
        }
    }
    __syncthreads();
}

__device__ __forceinline__ float wred(float v) {
    v += __shfl_xor_sync(0xffffffffu, v, 16);
    v += __shfl_xor_sync(0xffffffffu, v, 8);
    v += __shfl_xor_sync(0xffffffffu, v, 4);
    v += __shfl_xor_sync(0xffffffffu, v, 2);
    v += __shfl_xor_sync(0xffffffffu, v, 1);
    return v;
}

__device__ __forceinline__ float sigm(float x) { return 1.0f / (1.0f + expf(-x)); }

// ---------------- weight conversion fp32 -> fp16 (straight copy, vectorized) ---------
__global__ void convert_weights(const float* __restrict__ Whh0,
                                const float* __restrict__ Wih1,
                                const float* __restrict__ Whh1) {
    const size_t per4 = (size_t)FOURH * Hd / 4;     // float4 groups per matrix
    size_t idx = (size_t)blockIdx.x * blockDim.x + threadIdx.x;
    if (idx >= 3 * per4) return;
    int which = (int)(idx / per4);
    size_t g = idx % per4;
    const float* src = (which == 0) ? Whh0 : (which == 1) ? Wih1 : Whh1;
    float4 v = ((const float4*)src)[g];
    __half2 lo = __floats2half2_rn(v.x, v.y);
    __half2 hi = __floats2half2_rn(v.z, v.w);
    __half2* dst = (__half2*)g_Wh[which];
    dst[g * 2 + 0] = lo;
    dst[g * 2 + 1] = hi;
}

// ---------------- Kernel: x_pre0 GEMM (unchanged) ----------------
__global__ void gemm_xpre(const float* __restrict__ batch,
                          const float* __restrict__ Wih0,
                          const float* __restrict__ bih0,
                          const float* __restrict__ bhh0) {
    const int BM = 64, BN = 64, BK = 32;
    __shared__ float Xs[BM][BK + 1];
    __shared__ float Ws[BN][BK + 1];

    int tid = threadIdx.x;
    int nb = blockIdx.x * BN;
    int mb = blockIdx.y * BM;
    int tx = tid % 16, ty = tid / 16;

    float acc[4][4];
#pragma unroll
    for (int i = 0; i < 4; i++)
#pragma unroll
        for (int jj = 0; jj < 4; jj++) acc[i][jj] = 0.0f;

    for (int k0 = 0; k0 < 256; k0 += BK) {
#pragma unroll
        for (int i = 0; i < 8; i++) {
            int idx = tid + i * 256;
            int r = idx >> 5, kk = idx & 31;
            int m = mb + r;
            float v = 0.0f;
            if (m < NS) {
                int ei = m >> 4, bb = m & 15;
                v = batch[(size_t)bb * (64 * 256) + (size_t)(ei + 1) * 256 + (k0 + kk)];
            }
            Xs[r][kk] = v;
        }
#pragma unroll
        for (int i = 0; i < 8; i++) {
            int idx = tid + i * 256;
            int r = idx >> 5, kk = idx & 31;
            Ws[r][kk] = Wih0[(size_t)(nb + r) * 256 + (k0 + kk)];
        }
        __syncthreads();
#pragma unroll
        for (int kk = 0; kk < BK; kk++) {
            float xv[4], wv[4];
#pragma unroll
            for (int i = 0; i < 4; i++) xv[i] = Xs[ty * 4 + i][kk];
#pragma unroll
            for (int jj = 0; jj < 4; jj++) wv[jj] = Ws[tx * 4 + jj][kk];
#pragma unroll
            for (int i = 0; i < 4; i++)
#pragma unroll
                for (int jj = 0; jj < 4; jj++) acc[i][jj] += xv[i] * wv[jj];
        }
        __syncthreads();
    }
#pragma unroll
    for (int i = 0; i < 4; i++) {
        int m = mb + ty * 4 + i;
        if (m >= NS) continue;
#pragma unroll
        for (int jj = 0; jj < 4; jj++) {
            int n = nb + tx * 4 + jj;
            g_xpre[(size_t)m * FOURH + n] = acc[i][jj] + bih0[n] + bhh0[n];
        }
    }
}

// ---------------- one 256-wide chunk via HFMA2 ----------------
// Lane owns 8 consecutive k: k0 = kbase + lane*8. h read once (LDS.128, 4 half2),
// shared across the 4 gate rows. Per gate: HMUL2 + 3x HFMA2 (fp16 chain of 4),
// then fold into fp32 acc.
__device__ __forceinline__ void mv_chunk_h2(const __half* w0, const __half* w1,
                                            const __half* w2, const __half* w3,
                                            const __half* __restrict__ shh,
                                            int kbase, int lane, float acc[4]) {
    uint4 hu = *(const uint4*)(shh + kbase + lane * 8);
    const __half2* h2 = (const __half2*)&hu;
#pragma unroll
    for (int t = 0; t < 4; t++) {
        const __half* rp = (t == 0) ? w0 : (t == 1) ? w1 : (t == 2) ? w2 : w3;
        uint4 wu = *(const uint4*)(rp + lane * 8);
        const __half2* wv = (const __half2*)&wu;
        __half2 a = __hmul2(wv[0], h2[0]);
        a = __hfma2(wv[1], h2[1], a);
        a = __hfma2(wv[2], h2[2], a);
        a = __hfma2(wv[3], h2[3], a);
        float2 f = __half22float2(a);
        acc[t] += f.x + f.y;
    }
}

// full 1536-wide 4-row matvec: streamed chunks (L2) first for早 MLP, then smem chunks
__device__ __forceinline__ void mv4_hybrid(const __half* __restrict__ scache,
                                           const __half* __restrict__ gW, int j,
                                           const __half* __restrict__ shh, int lane,
                                           float acc[4]) {
    const __half* r0 = gW + (size_t)(0 * Hd + j) * Hd;
    const __half* r1 = gW + (size_t)(1 * Hd + j) * Hd;
    const __half* r2 = gW + (size_t)(2 * Hd + j) * Hd;
    const __half* r3 = gW + (size_t)(3 * Hd + j) * Hd;
#pragma unroll
    for (int cc = SC; cc < CHUNKS; cc++) {
        mv_chunk_h2(r0 + cc * 256, r1 + cc * 256, r2 + cc * 256, r3 + cc * 256,
                    shh, cc * 256, lane, acc);
    }
#pragma unroll
    for (int cc = 0; cc < SC; cc++) {
        const __half* base = scache + cc * 4 * 256;
        mv_chunk_h2(base + 0 * 256, base + 1 * 256, base + 2 * 256, base + 3 * 256,
                    shh, cc * 256, lane, acc);
    }
}

// ---------------- persistent sequential LSTM ----------------
// Iteration it:
//   L0 warps: h0(it) from h0(it-1)                         [it < NS]
//   A  warps: pa(it-1) = Wih1 . h0(it-1)                   [1 <= it <= NS]
//   B  warps: finalize step it-2: Whh1 . h1(it-3) + pa     [it >= 2]
__global__ __launch_bounds__(1024, 1)
void lstm_seq(const float* __restrict__ bih1,
              const float* __restrict__ bhh1,
              float* __restrict__ out,
              int G) {
    extern __shared__ unsigned char dynsmem[];
    __half* sh0h   = (__half*)dynsmem;              // 1536 half
    __half* sh1h   = sh0h + Hd;                     // 1536 half
    __half* wcache = sh1h + Hd;                     // 32 * WC_PER_WARP halves

    int tid  = threadIdx.x;
    int b    = blockIdx.x;
    int warp = tid >> 5;
    int lane = tid & 31;

    for (int i = tid; i < Hd; i += 1024) {
        g_h0[0][i] = 0.0f; g_h0[1][i] = 0.0f;
        g_h1[0][i] = 0.0f; g_h1[1][i] = 0.0f;
    }
    for (int i = tid + b * 1024; i < FOURH; i += 1024 * G) {
        g_pa[0][i] = 0.0f; g_pa[1][i] = 0.0f;
    }

    int u = warp * G + b;
    bool isL0 = (u < Hd);
    bool isA  = (u >= Hd)     && (u < 2 * Hd);
    bool isB  = (u >= 2 * Hd) && (u < 3 * Hd);
    bool active = isL0 || isA || isB;
    int j = isL0 ? u : isA ? (u - Hd) : (u - 2 * Hd);

    const __half* gW = isL0 ? g_Wh[0] : isA ? g_Wh[1] : g_Wh[2];
    __half* scache = wcache + (size_t)warp * WC_PER_WARP;

    // fill per-warp smem cache: chunks 0..SC-1, 4 gate segments (straight copy)
    if (active) {
#pragma unroll
        for (int cc = 0; cc < SC; cc++) {
#pragma unroll
            for (int t = 0; t < 4; t++) {
                const __half* src = gW + (size_t)(t * Hd + j) * Hd + cc * 256 + lane * 8;
                __half* dst = scache + (cc * 4 + t) * 256 + lane * 8;
                *(uint4*)dst = *(const uint4*)src;
            }
        }
    }

    float bi = 0.f, bf = 0.f, bg = 0.f, bo = 0.f;
    if (isB) {
        bi = bih1[0 * Hd + j] + bhh1[0 * Hd + j];
        bf = bih1[1 * Hd + j] + bhh1[1 * Hd + j];
        bg = bih1[2 * Hd + j] + bhh1[2 * Hd + j];
        bo = bih1[3 * Hd + j] + bhh1[3 * Hd + j];
    }

    grid_barrier(G);

    float c = 0.0f, h = 0.0f;   // register-resident cell state

    for (int it = 0; it <= NS + 1; ++it) {
        int rp = (it + 1) & 1;   // read parity
        int wp = it & 1;         // write parity

        // ---- hoisted loads independent of staged h (hide L2/DRAM latency) ----
        float xpi = 0.f, xpf = 0.f, xpg = 0.f, xpo = 0.f;
        if (isL0 && it < NS) {
            const float* xp = g_xpre + (size_t)it * FOURH;
            xpi = xp[0 * Hd + j];
            xpf = xp[1 * Hd + j];
            xpg = xp[2 * Hd + j];
            xpo = xp[3 * Hd + j];
        }
        float pai = 0.f, paf = 0.f, pag = 0.f, pao = 0.f;
        if (isB && it >= 2) {
            volatile const float* pa = g_pa[rp];   // written at it-1
            pai = pa[0 * Hd + j];
            paf = pa[1 * Hd + j];
            pag = pa[2 * Hd + j];
            pao = pa[3 * Hd + j];
        }

        // ---- stage h (fp32 in L2 -> fp16 in smem) ----
        {
            volatile const float* vh0 = g_h0[rp];
            volatile const float* vh1 = g_h1[rp];
            for (int i = tid; i < Hd; i += 1024) {   // i indexes half2 slots (1536 total)
                if (i < Hd / 2) {
                    float a = vh0[2 * i], bb2 = vh0[2 * i + 1];
                    ((__half2*)sh0h)[i] = __floats2half2_rn(a, bb2);
                } else {
                    int s = i - Hd / 2;
                    float a = vh1[2 * s], bb2 = vh1[2 * s + 1];
                    ((__half2*)sh1h)[s] = __floats2half2_rn(a, bb2);
                }
            }
        }
        __syncthreads();

        if (isL0) {
            if (it < NS) {
                float acc[4] = {0.f, 0.f, 0.f, 0.f};
                mv4_hybrid(scache, gW, j, sh0h, lane, acc);
                float pi = wred(acc[0]) + xpi;
                float pf = wred(acc[1]) + xpf;
                float pg = wred(acc[2]) + xpg;
                float po = wred(acc[3]) + xpo;
                c = sigm(pf) * c + sigm(pi) * tanhf(pg);
                h = sigm(po) * tanhf(c);
                if (lane == 0) ((volatile float*)g_h0[wp])[j] = h;
            }
        } else if (isA) {
            if (it >= 1 && it <= NS) {
                float acc[4] = {0.f, 0.f, 0.f, 0.f};
                mv4_hybrid(scache, gW, j, sh0h, lane, acc);
                float pi = wred(acc[0]);
                float pf = wred(acc[1]);
                float pg = wred(acc[2]);
                float po = wred(acc[3]);
                if (lane == 0) {
                    volatile float* pa = g_pa[wp];
                    pa[0 * Hd + j] = pi;
                    pa[1 * Hd + j] = pf;
                    pa[2 * Hd + j] = pg;
                    pa[3 * Hd + j] = po;
                }
            }
        } else if (isB) {
            if (it >= 2) {
                float acc[4] = {0.f, 0.f, 0.f, 0.f};
                mv4_hybrid(scache, gW, j, sh1h, lane, acc);
                float pi = wred(acc[0]) + pai + bi;
                float pf = wred(acc[1]) + paf + bf;
                float pg = wred(acc[2]) + pag + bg;
                float po = wred(acc[3]) + pao + bo;
                if (lane == 0) {
                    c = sigm(pf) * c + sigm(pi) * tanhf(pg);
                    h = sigm(po) * tanhf(c);
                    ((volatile float*)g_h1[wp])[j] = h;
                }
            }
        }

        grid_barrier(G);
    }

    // out layout: [h0 | h1 | c0 | c1]
    if (lane == 0) {
        if (isL0) { out[j] = h;      out[2 * Hd + j] = c; }
        if (isB)  { out[Hd + j] = h; out[3 * Hd + j] = c; }
    }
}

// ---------------- launch ----------------
extern "C" void kernel_launch(void* const* d_in, const int* in_sizes, int n_in,
                              void* d_out, int out_size) {
    const float* batch = (const float*)d_in[0];
    const float* Wih0  = (const float*)d_in[1];
    const float* Whh0  = (const float*)d_in[2];
    const float* bih0  = (const float*)d_in[3];
    const float* bhh0  = (const float*)d_in[4];
    const float* Wih1  = (const float*)d_in[5];
    const float* Whh1  = (const float*)d_in[6];
    const float* bih1  = (const float*)d_in[7];
    const float* bhh1  = (const float*)d_in[8];
    float* out = (float*)d_out;

    int dev = 0;
    cudaGetDevice(&dev);
    int G = 0;
    cudaDeviceGetAttribute(&G, cudaDevAttrMultiProcessorCount, dev);
    if (G <= 0) G = 148;

    static int smem_set = 0;
    if (!smem_set) {
        cudaFuncSetAttribute(lstm_seq, cudaFuncAttributeMaxDynamicSharedMemorySize,
                             SMEM_BYTES);
        smem_set = 1;
    }

    size_t groups = (size_t)3 * FOURH * Hd / 4;
    int cvt_blocks = (int)((groups + 255) / 256);
    convert_weights<<<cvt_blocks, 256>>>(Whh0, Wih1, Whh1);

    dim3 g1(FOURH / 64, (NS + 63) / 64);
    gemm_xpre<<<g1, 256>>>(batch, Wih0, bih0, bhh0);

    lstm_seq<<<G, 1024, SMEM_BYTES>>>(bih1, bhh1, out, G);
}